// round 4
// baseline (speedup 1.0000x reference)
#include <cuda_runtime.h>

// Radon forward projection:
//   image (2,1,256,256) f32 -> sinogram (2,1,363,180) f32
// S=363; padded image occupies padded coords [53,309).
// px(i,j) = c*(j-181) + s*(i-181) + 181 ; py(i,j) = -s*(j-181) + c*(i-181) + 181
// out[b,0,j,t] = sum_i bilinear(padded_img_b, py, px)
//
// Round-3: CTA = (32 j) x (64 i chunk) patch for one angle. Rotated footprint
// bbox (<= ~5180 px, proven bound) is staged into two smem planes (zero-filled
// outside the image), then all bilinear taps are conflict-free LDS. Uniform
// inner loop (no boundary predication). Chunk skipped if bbox misses image.

namespace {
constexpr int   kS     = 363;
constexpr int   kT     = 180;
constexpr float kMagic = 8388608.0f;   // 2^23
constexpr int   kPlane = 5248;         // floats per batch plane (>= max W*H = ~5180)
}

__global__ void __launch_bounds__(256) radon_fwd(const float* __restrict__ img,
                                                 float* __restrict__ out)
{
    extern __shared__ float sm[];          // [2 * kPlane]
    __shared__ float red[2][32][9];        // padded to 9: conflict-free reduce

    const int tid   = threadIdx.x;
    const int th    = blockIdx.y;          // angle
    const int jbase = blockIdx.x * 32;
    const int jl    = tid & 31;
    const int io    = tid >> 5;            // i-phase 0..7
    const int j     = jbase + jl;

    const float theta = (float)th * (180.0f / 179.0f) * 0.017453292519943295f;
    float s, c;
    sincosf(theta, &s, &c);

    const float cb = fmaf(-181.0f, s, 181.0f);
    const float sb = fmaf(-181.0f, c, 181.0f);
    const float fj = (float)j - 181.0f;
    const float px_base = fmaf(c,  fj, cb);
    const float py_base = fmaf(-s, fj, sb);

    // tile-corner base coords (j = jbase .. jbase+31)
    const float fj0 = (float)jbase - 181.0f;
    const float fj1 = fj0 + 31.0f;
    const float qx0 = fmaf(c,  fj0, cb), qx1 = fmaf(c,  fj1, cb);
    const float qy0 = fmaf(-s, fj0, sb), qy1 = fmaf(-s, fj1, sb);
    const float pxlo = fminf(qx0, qx1), pxhi = fmaxf(qx0, qx1);
    const float pylo = fminf(qy0, qy1), pyhi = fmaxf(qy0, qy1);

    float acc0 = 0.0f, acc1 = 0.0f;

    for (int i0 = 0; i0 < kS; i0 += 64) {
        const int i1 = min(i0 + 63, kS - 1);
        const float fi0 = (float)i0, fi1 = (float)i1;
        const float sx0 = s * fi0, sx1 = s * fi1;
        const float cy0 = c * fi0, cy1 = c * fi1;
        const float bxlo = pxlo + fminf(sx0, sx1);
        const float bxhi = pxhi + fmaxf(sx0, sx1);
        const float bylo = pylo + fminf(cy0, cy1);
        const float byhi = pyhi + fmaxf(cy0, cy1);

        const int x0 = (int)floorf(bxlo) - 1;
        const int y0 = (int)floorf(bylo) - 1;
        int W = ((int)floorf(bxhi) + 2) - x0 + 1;
        int H = ((int)floorf(byhi) + 2) - y0 + 1;
        W |= 1;                                  // odd pitch: conflict-free LDS

        // skip chunk entirely if footprint cannot touch the image
        if (x0 + W <= 53 || x0 >= 309 || y0 + H <= 53 || y0 >= 309) continue;

        if (W * H > kPlane) H = kPlane / W;      // safety; never triggers

        __syncthreads();                         // smem reuse barrier

        // stage footprint into smem planes, zero outside image [53,309)^2
        {
            const int tot = W * H;
            int x = tid % W;
            int y = tid / W;
            for (int p = tid; p < tot; p += 256) {
                const int gx = x0 + x - 53;
                const int gy = y0 + y - 53;
                float a = 0.0f, b = 0.0f;
                if ((unsigned)gx < 256u && (unsigned)gy < 256u) {
                    const int g = gy * 256 + gx;
                    a = img[g];
                    b = img[g + 65536];
                }
                sm[p]          = a;
                sm[kPlane + p] = b;
                x += 256;
                while (x >= W) { x -= W; ++y; }
            }
        }
        __syncthreads();

        const float lxb = px_base - (float)x0;
        const float lyb = py_base - (float)y0;
        const float* __restrict__ pB = sm + kPlane;

        for (int i = i0 + io; i <= i1; i += 8) {
            const float fi  = (float)i;
            const float lx  = fmaf(s, fi, lxb);
            const float ly  = fmaf(c, fi, lyb);
            const float flx = __fadd_rz(lx, kMagic);
            const float fly = __fadd_rz(ly, kMagic);
            const float xf  = flx - kMagic, yf = fly - kMagic;
            const float wx1 = lx - xf,      wy1 = ly - yf;
            const float wx0 = 1.0f - wx1,   wy0 = 1.0f - wy1;
            const int ix = (int)(__float_as_uint(flx) & 0xFFFFu);
            const int iy = (int)(__float_as_uint(fly) & 0xFFFFu);
            const int a0 = iy * W + ix;
            const int a1 = a0 + W;
            const float v00 = sm[a0], v01 = sm[a0 + 1];
            const float v10 = sm[a1], v11 = sm[a1 + 1];
            const float u00 = pB[a0], u01 = pB[a0 + 1];
            const float u10 = pB[a1], u11 = pB[a1 + 1];
            const float h0 = fmaf(wx1, v01, wx0 * v00);
            const float h1 = fmaf(wx1, v11, wx0 * v10);
            acc0 = fmaf(wy0, h0, acc0);
            acc0 = fmaf(wy1, h1, acc0);
            const float g0 = fmaf(wx1, u01, wx0 * u00);
            const float g1 = fmaf(wx1, u11, wx0 * u10);
            acc1 = fmaf(wy0, g0, acc1);
            acc1 = fmaf(wy1, g1, acc1);
        }
    }

    // reduce the 8 i-phases
    red[0][jl][io] = acc0;
    red[1][jl][io] = acc1;
    __syncthreads();
    if (tid < 64) {
        const int b  = tid >> 5;
        const int jj = tid & 31;
        float sum = 0.0f;
        #pragma unroll
        for (int k = 0; k < 8; ++k) sum += red[b][jj][k];
        const int jo = jbase + jj;
        if (jo < kS) out[(b * kS + jo) * kT + th] = sum;
    }
}

extern "C" void kernel_launch(void* const* d_in, const int* in_sizes, int n_in,
                              void* d_out, int out_size)
{
    const float* img = (const float*)d_in[0];
    float* out = (float*)d_out;
    dim3 grid((kS + 31) / 32, kT);
    radon_fwd<<<grid, 256, 2 * kPlane * sizeof(float)>>>(img, out);
}

// round 5
// speedup vs baseline: 1.1418x; 1.1418x over previous
#include <cuda_runtime.h>

// Radon forward projection:
//   image (2,1,256,256) f32 -> sinogram (2,1,363,180) f32
// S=363; padded image region = padded coords [53,309).
// px(i,j) = c*(j-181) + s*(i-181) + 181 ; py(i,j) = -s*(j-181) + c*(i-181) + 181
// out[b,0,j,t] = sum_i bilinear(padded_img_b, py, px)
//
// R5 = R3 winner (warp (J,I) patch shapes minimizing row span) with the
// interior gather quad-vectorized: per sample 4x LDG.128 + tent-weight dot
// products replace 8x LDG.32, cutting L1tex wavefronts ~1.5x.

namespace {
constexpr int   kS = 363;
constexpr int   kT = 180;
constexpr float kMagic = 8388608.0f;   // 2^23
}

__global__ void __launch_bounds__(128) radon_fwd(const float* __restrict__ img,
                                                 float* __restrict__ out)
{
    const int t    = threadIdx.x;
    const int th   = blockIdx.y;              // angle index
    const int jbase = blockIdx.x * 16;

    const float theta = (float)th * (180.0f / 179.0f) * 0.017453292519943295f;
    float s, c;
    sincosf(theta, &s, &c);
    const float as = fabsf(s), ac = fabsf(c);

    // pick warp patch shape minimizing row-span J*|s| + I*|c|
    const float span0 = 16.f * as + 2.f * ac;   // (J,I)=(16,2)
    const float span1 =  8.f * as + 4.f * ac;   // (8,4)
    const float span2 =  4.f * as + 8.f * ac;   // (4,8)
    int jl, io;
    if (span0 <= span1 && span0 <= span2) {
        jl = t & 15;  io = t >> 4;
    } else if (span1 <= span2) {
        const int w = t >> 5;
        jl = (t & 7) | ((w & 1) << 3);
        io = ((t >> 3) & 3) | ((w >> 1) << 2);
    } else {
        const int w = t >> 5;
        io = t & 7;
        jl = ((t >> 3) & 3) | (w << 2);
    }

    const int j = jbase + jl;

    const float fj = (float)j - 181.0f;
    const float px_base = fmaf(c, fj, fmaf(-181.0f, s, 181.0f));
    const float py_base = fmaf(-s, fj, fmaf(-181.0f, c, 181.0f));

    // ---- outer clip: i-range where any tap can be nonzero ----
    float lo = 0.0f, hi = 362.0f;
    bool empty = (j >= kS);
    {
        float d = s, b = px_base;
        #pragma unroll
        for (int axis = 0; axis < 2; ++axis) {
            if (fabsf(d) < 1e-7f) {
                if (b <= 52.0f || b >= 309.0f) empty = true;
            } else {
                float t0 = (52.0f  - b) / d;
                float t1 = (309.0f - b) / d;
                lo = fmaxf(lo, fminf(t0, t1));
                hi = fminf(hi, fmaxf(t0, t1));
            }
            d = c; b = py_base;
        }
    }
    lo = fmaxf(lo, 0.0f);
    hi = fminf(hi, 362.0f);

    int i_lo = 0, i_hi = -1;
    if (!empty && lo <= hi + 1.0f) {
        i_lo = max(0,   (int)floorf(lo) - 1);
        i_hi = min(362, (int)ceilf(hi) + 1);
    }

    // ---- interior clip: all 4 taps strictly inside image ----
    int in_lo = i_hi + 1, in_hi = i_hi;
    if (i_lo <= i_hi) {
        float lo2 = (float)i_lo, hi2 = (float)i_hi;
        bool iempty = false;
        float d = s, b = px_base;
        #pragma unroll
        for (int axis = 0; axis < 2; ++axis) {
            if (fabsf(d) < 1e-7f) {
                if (b < 53.0f || b >= 308.0f) iempty = true;
            } else {
                float t0 = (53.0f   - b) / d;
                float t1 = (307.99f - b) / d;
                lo2 = fmaxf(lo2, fminf(t0, t1));
                hi2 = fminf(hi2, fmaxf(t0, t1));
            }
            d = c; b = py_base;
        }
        if (!iempty) {
            lo2 = fmaxf(lo2, 0.0f);
            hi2 = fminf(hi2, 362.0f);
            in_lo = max((int)ceilf(lo2),  i_lo);
            in_hi = min((int)floorf(hi2), i_hi);
            while (in_lo <= in_hi) {
                float px = fmaf(s, (float)in_lo, px_base);
                float py = fmaf(c, (float)in_lo, py_base);
                if (px >= 53.0f && px < 308.0f && py >= 53.0f && py < 308.0f) break;
                ++in_lo;
            }
            while (in_hi >= in_lo) {
                float px = fmaf(s, (float)in_hi, px_base);
                float py = fmaf(c, (float)in_hi, py_base);
                if (px >= 53.0f && px < 308.0f && py >= 53.0f && py < 308.0f) break;
                --in_hi;
            }
            if (in_lo > in_hi) { in_lo = i_hi + 1; in_hi = i_hi; }
        }
    }

    float acc0 = 0.0f, acc1 = 0.0f;
    const float4* __restrict__ P4 = reinterpret_cast<const float4*>(img);

    auto sample_checked = [&](int i) {
        float fi = (float)i;
        float px = fmaf(s, fi, px_base);
        float py = fmaf(c, fi, py_base);
        float xf = floorf(px), yf = floorf(py);
        int   x0 = (int)xf,    y0 = (int)yf;
        float wx1 = px - xf,   wy1 = py - yf;
        float wx0 = 1.0f - wx1, wy0 = 1.0f - wy1;
        int xi0 = x0 - 53, yi0 = y0 - 53;
        bool vx0 = (unsigned)xi0       < 256u;
        bool vx1 = (unsigned)(xi0 + 1) < 256u;
        bool vy0 = (unsigned)yi0       < 256u;
        bool vy1 = (unsigned)(yi0 + 1) < 256u;
        int base = yi0 * 256 + xi0;
        float w00 = wy0 * wx0, w01 = wy0 * wx1;
        float w10 = wy1 * wx0, w11 = wy1 * wx1;
        if (vy0 && vx0) { acc0 = fmaf(img[base],           w00, acc0); acc1 = fmaf(img[base + 65536],       w00, acc1); }
        if (vy0 && vx1) { acc0 = fmaf(img[base + 1],       w01, acc0); acc1 = fmaf(img[base + 65537],       w01, acc1); }
        if (vy1 && vx0) { acc0 = fmaf(img[base + 256],     w10, acc0); acc1 = fmaf(img[base + 65536 + 256], w10, acc1); }
        if (vy1 && vx1) { acc0 = fmaf(img[base + 257],     w11, acc0); acc1 = fmaf(img[base + 65536 + 257], w11, acc1); }
    };

    // strided loop: this thread owns i-phase `io`, stride 8
    const int i0 = i_lo + ((io - i_lo) & 7);
    for (int i = i0; i <= i_hi; i += 8) {
        if (i >= in_lo && i <= in_hi) {
            const float fi = (float)i;
            const float px = fmaf(s, fi, px_base);
            const float py = fmaf(c, fi, py_base);
            const float fx = __fadd_rz(px, kMagic);
            const float fy = __fadd_rz(py, kMagic);
            const float yf = fy - kMagic;
            const float wy1 = py - yf;
            const float wy0 = 1.0f - wy1;
            const int ix = (int)(__float_as_uint(fx) & 0xFFFFu) - 53;  // [0,254]
            const int iy = (int)(__float_as_uint(fy) & 0xFFFFu) - 53;  // [0,254]
            const int xq = ix & ~3;
            const float fxl = (px - 53.0f) - (float)xq;                // [0,4)
            // tent weights over the aligned quad (wx0 at pos r, wx1 at r+1)
            const float W0 = fmaxf(0.0f, 1.0f - fabsf(fxl));
            const float W1 = fmaxf(0.0f, 1.0f - fabsf(fxl - 1.0f));
            const float W2 = fmaxf(0.0f, 1.0f - fabsf(fxl - 2.0f));
            const float W3 = fmaxf(0.0f, 1.0f - fabsf(fxl - 3.0f));
            const float W4 = fmaxf(0.0f, fxl - 3.0f);                  // straddle
            const int q0 = iy * 64 + (xq >> 2);                        // float4 idx
            const float4 A0 = P4[q0];            // batch0, row y0
            const float4 A1 = P4[q0 + 64];       // batch0, row y0+1
            const float4 B0 = P4[q0 + 16384];    // batch1, row y0
            const float4 B1 = P4[q0 + 16448];    // batch1, row y0+1
            float h0 = W0 * A0.x;
            h0 = fmaf(W1, A0.y, h0); h0 = fmaf(W2, A0.z, h0); h0 = fmaf(W3, A0.w, h0);
            float h1 = W0 * A1.x;
            h1 = fmaf(W1, A1.y, h1); h1 = fmaf(W2, A1.z, h1); h1 = fmaf(W3, A1.w, h1);
            float g0 = W0 * B0.x;
            g0 = fmaf(W1, B0.y, g0); g0 = fmaf(W2, B0.z, g0); g0 = fmaf(W3, B0.w, g0);
            float g1 = W0 * B1.x;
            g1 = fmaf(W1, B1.y, g1); g1 = fmaf(W2, B1.z, g1); g1 = fmaf(W3, B1.w, g1);
            if (W4 > 0.0f) {
                // x0&3==3: x0+1 lives in the next quad (always in-bounds: x0<=251 here)
                const int ea = (q0 << 2) + 4;
                h0 = fmaf(W4, img[ea],         h0);
                h1 = fmaf(W4, img[ea + 256],   h1);
                g0 = fmaf(W4, img[ea + 65536], g0);
                g1 = fmaf(W4, img[ea + 65792], g1);
            }
            acc0 = fmaf(wy0, h0, acc0);
            acc0 = fmaf(wy1, h1, acc0);
            acc1 = fmaf(wy0, g0, acc1);
            acc1 = fmaf(wy1, g1, acc1);
        } else {
            sample_checked(i);
        }
    }

    // ---- reduction over the 8 i-phases via smem ----
    __shared__ float red[2][16][9];   // pad to 9: conflict-free
    red[0][jl][io] = acc0;
    red[1][jl][io] = acc1;
    __syncthreads();

    if (t < 32) {
        const int b  = t >> 4;
        const int jj = t & 15;
        float sum = 0.0f;
        #pragma unroll
        for (int k = 0; k < 8; ++k) sum += red[b][jj][k];
        const int jo = jbase + jj;
        if (jo < kS) out[(b * kS + jo) * kT + th] = sum;
    }
}

extern "C" void kernel_launch(void* const* d_in, const int* in_sizes, int n_in,
                              void* d_out, int out_size)
{
    const float* img = (const float*)d_in[0];
    float* out = (float*)d_out;
    dim3 grid((kS + 15) / 16, kT);
    radon_fwd<<<grid, 128>>>(img, out);
}

// round 7
// speedup vs baseline: 2.3302x; 2.0407x over previous
#include <cuda_runtime.h>

// Radon forward projection:
//   image (2,1,256,256) f32 -> sinogram (2,1,363,180) f32
// S=363; padded image occupies padded coords [53,309).
// px(i,j) = c*(j-181) + s*(i-181) + 181 ; py(i,j) = -s*(j-181) + c*(i-181) + 181
// out[b,0,j,t] = sum_i bilinear(padded_img_b, py, px)
//
// R6: repack kernel builds a batch-interleaved float2 buffer with a zero
// border covering padded coords [50,313) in both axes. Main kernel = R3
// warp-patch gather, but each bilinear tap is ONE LDG.64 (both batches),
// 4 loads/sample total, and the zero border makes the gather path uniform
// (no interior/edge split, no predication).

namespace {
constexpr int   kS     = 363;
constexpr int   kT     = 180;
constexpr float kMagic = 8388608.0f;   // 2^23
constexpr int   kBW    = 264;          // buffer pitch (float2 elems)
constexpr int   kBH    = 263;          // buffer rows
// buffer (bx,by) covers padded coords (50+bx, 50+by); image at bx,by in [3,259)
constexpr unsigned kOffC = (unsigned)(0u - (0x4B000000u * (unsigned)kBW + 0x4B000000u) - 13250u);
// off = (y0-50)*kBW + (x0-50); 13250 = 50*264 + 50
}

__device__ float2 g_buf[kBH * kBW];

__global__ void repack(const float* __restrict__ img)
{
    const int idx = blockIdx.x * blockDim.x + threadIdx.x;
    if (idx >= kBH * kBW) return;
    const int y = idx / kBW;
    const int x = idx - y * kBW;
    const int gx = x - 3;             // image coords
    const int gy = y - 3;
    float2 v = make_float2(0.0f, 0.0f);
    if ((unsigned)gx < 256u && (unsigned)gy < 256u) {
        const int g = gy * 256 + gx;
        v.x = img[g];
        v.y = img[g + 65536];
    }
    g_buf[idx] = v;
}

__global__ void __launch_bounds__(128) radon_fwd(float* __restrict__ out)
{
    const int t     = threadIdx.x;
    const int th    = blockIdx.y;             // angle index
    const int jbase = blockIdx.x * 16;

    const float theta = (float)th * (180.0f / 179.0f) * 0.017453292519943295f;
    float s, c;
    sincosf(theta, &s, &c);
    const float as = fabsf(s), ac = fabsf(c);

    // pick warp patch shape minimizing image-row span J*|s| + I*|c|
    const float span0 = 16.f * as + 2.f * ac;   // (J,I)=(16,2)
    const float span1 =  8.f * as + 4.f * ac;   // (8,4)
    const float span2 =  4.f * as + 8.f * ac;   // (4,8)
    int jl, io;
    if (span0 <= span1 && span0 <= span2) {
        jl = t & 15;  io = t >> 4;
    } else if (span1 <= span2) {
        const int w = t >> 5;
        jl = (t & 7) | ((w & 1) << 3);
        io = ((t >> 3) & 3) | ((w >> 1) << 2);
    } else {
        const int w = t >> 5;
        io = t & 7;
        jl = ((t >> 3) & 3) | (w << 2);
    }

    const int j = jbase + jl;

    const float fj = (float)j - 181.0f;
    const float px_base = fmaf(c, fj, fmaf(-181.0f, s, 181.0f));
    const float py_base = fmaf(-s, fj, fmaf(-181.0f, c, 181.0f));

    // ---- outer clip: i-range where any tap can be nonzero (px,py in (52,309)) ----
    float lo = 0.0f, hi = 362.0f;
    bool empty = (j >= kS);
    {
        float d = s, b = px_base;
        #pragma unroll
        for (int axis = 0; axis < 2; ++axis) {
            if (fabsf(d) < 1e-7f) {
                if (b <= 52.0f || b >= 309.0f) empty = true;
            } else {
                float t0 = (52.0f  - b) / d;
                float t1 = (309.0f - b) / d;
                lo = fmaxf(lo, fminf(t0, t1));
                hi = fminf(hi, fmaxf(t0, t1));
            }
            d = c; b = py_base;
        }
    }
    lo = fmaxf(lo, 0.0f);
    hi = fminf(hi, 362.0f);

    int i_lo = 0, i_hi = -1;
    if (!empty && lo <= hi + 1.0f) {
        i_lo = max(0,   (int)floorf(lo) - 1);   // px,py stay within [50,311] here
        i_hi = min(362, (int)ceilf(hi) + 1);
    }

    float acc0 = 0.0f, acc1 = 0.0f;
    const float2* __restrict__ B2 = g_buf;

    // strided loop: this thread owns i-phase `io`, stride 8; uniform gather
    const int i0 = i_lo + ((io - i_lo) & 7);
    #pragma unroll 2
    for (int i = i0; i <= i_hi; i += 8) {
        const float fi = (float)i;
        const float px = fmaf(s, fi, px_base);
        const float py = fmaf(c, fi, py_base);
        const float fx = __fadd_rz(px, kMagic);   // floor (px >= 50 > 0)
        const float fy = __fadd_rz(py, kMagic);
        const float xf = fx - kMagic, yf = fy - kMagic;
        const float wx1 = px - xf,    wy1 = py - yf;
        const float wx0 = 1.0f - wx1, wy0 = 1.0f - wy1;
        const unsigned xb = __float_as_uint(fx);
        const unsigned yb = __float_as_uint(fy);
        const int off = (int)(yb * (unsigned)kBW + xb + kOffC);
        const float2 a00 = B2[off];
        const float2 a01 = B2[off + 1];
        const float2 a10 = B2[off + kBW];
        const float2 a11 = B2[off + kBW + 1];
        const float h0 = fmaf(wx1, a01.x, wx0 * a00.x);
        const float h1 = fmaf(wx1, a11.x, wx0 * a10.x);
        acc0 = fmaf(wy0, h0, acc0);
        acc0 = fmaf(wy1, h1, acc0);
        const float g0 = fmaf(wx1, a01.y, wx0 * a00.y);
        const float g1 = fmaf(wx1, a11.y, wx0 * a10.y);
        acc1 = fmaf(wy0, g0, acc1);
        acc1 = fmaf(wy1, g1, acc1);
    }

    // ---- reduction over the 8 i-phases via smem ----
    __shared__ float red[2][16][9];   // pad to 9: conflict-free
    red[0][jl][io] = acc0;
    red[1][jl][io] = acc1;
    __syncthreads();

    if (t < 32) {
        const int b  = t >> 4;
        const int jj = t & 15;
        float sum = 0.0f;
        #pragma unroll
        for (int k = 0; k < 8; ++k) sum += red[b][jj][k];
        const int jo = jbase + jj;
        if (jo < kS) out[(b * kS + jo) * kT + th] = sum;
    }
}

extern "C" void kernel_launch(void* const* d_in, const int* in_sizes, int n_in,
                              void* d_out, int out_size)
{
    const float* img = (const float*)d_in[0];
    float* out = (float*)d_out;
    repack<<<(kBH * kBW + 255) / 256, 256>>>(img);
    dim3 grid((kS + 15) / 16, kT);
    radon_fwd<<<grid, 128>>>(out);
}

// round 8
// speedup vs baseline: 2.6239x; 1.1261x over previous
#include <cuda_runtime.h>

// Radon forward projection:
//   image (2,1,256,256) f32 -> sinogram (2,1,363,180) f32
// S=363; padded image occupies padded coords [53,309).
// px(i,j) = c*(j-181) + s*(i-181) + 181 ; py(i,j) = -s*(j-181) + c*(i-181) + 181
// out[b,0,j,t] = sum_i bilinear(padded_img_b, py, px)
//
// R7: repack builds a row-pair + batch interleaved float4 buffer with zero
// border: buf4[y][x] = (b0[y,x], b1[y,x], b0[y+1,x], b1[y+1,x]) over padded
// coords [50,313). One bilinear sample = TWO LDG.128 (all 8 taps), uniform
// path (zero border), R3/R6 warp-patch shapes + i-phase smem reduction.

namespace {
constexpr int   kS     = 363;
constexpr int   kT     = 180;
constexpr float kMagic = 8388608.0f;   // 2^23
constexpr int   kBW    = 264;          // buffer pitch (float4 elems)
constexpr int   kBH    = 263;          // buffer rows
// off = (y0-50)*kBW + (x0-50), with x0,y0 carried in low bits of magic floats:
constexpr unsigned kOffC = (unsigned)(0u - (0x4B000000u * (unsigned)kBW + 0x4B000000u) - 13250u);
}

__device__ float4 g_buf[kBH * kBW];

__global__ void repack(const float* __restrict__ img)
{
    const int idx = blockIdx.x * blockDim.x + threadIdx.x;
    if (idx >= kBH * kBW) return;
    const int y = idx / kBW;
    const int x = idx - y * kBW;
    const int gx  = x - 3;            // image coords
    const int gy  = y - 3;
    const int gy1 = gy + 1;
    float4 v = make_float4(0.0f, 0.0f, 0.0f, 0.0f);
    if ((unsigned)gx < 256u) {
        if ((unsigned)gy < 256u) {
            const int g = gy * 256 + gx;
            v.x = img[g];
            v.y = img[g + 65536];
        }
        if ((unsigned)gy1 < 256u) {
            const int g = gy1 * 256 + gx;
            v.z = img[g];
            v.w = img[g + 65536];
        }
    }
    g_buf[idx] = v;
}

__global__ void __launch_bounds__(128) radon_fwd(float* __restrict__ out)
{
    const int t     = threadIdx.x;
    const int th    = blockIdx.y;             // angle index
    const int jbase = blockIdx.x * 16;

    const float theta = (float)th * (180.0f / 179.0f) * 0.017453292519943295f;
    float s, c;
    sincosf(theta, &s, &c);
    const float as = fabsf(s), ac = fabsf(c);

    // pick warp patch shape minimizing image-row span J*|s| + I*|c|
    const float span0 = 16.f * as + 2.f * ac;   // (J,I)=(16,2)
    const float span1 =  8.f * as + 4.f * ac;   // (8,4)
    const float span2 =  4.f * as + 8.f * ac;   // (4,8)
    int jl, io;
    if (span0 <= span1 && span0 <= span2) {
        jl = t & 15;  io = t >> 4;
    } else if (span1 <= span2) {
        const int w = t >> 5;
        jl = (t & 7) | ((w & 1) << 3);
        io = ((t >> 3) & 3) | ((w >> 1) << 2);
    } else {
        const int w = t >> 5;
        io = t & 7;
        jl = ((t >> 3) & 3) | (w << 2);
    }

    const int j = jbase + jl;

    const float fj = (float)j - 181.0f;
    const float px_base = fmaf(c, fj, fmaf(-181.0f, s, 181.0f));
    const float py_base = fmaf(-s, fj, fmaf(-181.0f, c, 181.0f));

    // ---- outer clip: i-range where any tap can be nonzero (px,py in (52,309)) ----
    float lo = 0.0f, hi = 362.0f;
    bool empty = (j >= kS);
    {
        float d = s, b = px_base;
        #pragma unroll
        for (int axis = 0; axis < 2; ++axis) {
            if (fabsf(d) < 1e-7f) {
                if (b <= 52.0f || b >= 309.0f) empty = true;
            } else {
                float t0 = (52.0f  - b) / d;
                float t1 = (309.0f - b) / d;
                lo = fmaxf(lo, fminf(t0, t1));
                hi = fminf(hi, fmaxf(t0, t1));
            }
            d = c; b = py_base;
        }
    }
    lo = fmaxf(lo, 0.0f);
    hi = fminf(hi, 362.0f);

    int i_lo = 0, i_hi = -1;
    if (!empty && lo <= hi + 1.0f) {
        i_lo = max(0,   (int)floorf(lo) - 1);   // px,py stay within [50,311] here
        i_hi = min(362, (int)ceilf(hi) + 1);
    }

    float acc0 = 0.0f, acc1 = 0.0f;
    const float4* __restrict__ B4 = g_buf;

    // strided loop: this thread owns i-phase `io`, stride 8; uniform gather
    const int i0 = i_lo + ((io - i_lo) & 7);
    #pragma unroll 2
    for (int i = i0; i <= i_hi; i += 8) {
        const float fi = (float)i;
        const float px = fmaf(s, fi, px_base);
        const float py = fmaf(c, fi, py_base);
        const float fx = __fadd_rz(px, kMagic);   // floor (px >= 50 > 0)
        const float fy = __fadd_rz(py, kMagic);
        const float xf = fx - kMagic, yf = fy - kMagic;
        const float wx1 = px - xf,    wy1 = py - yf;
        const float wx0 = 1.0f - wx1, wy0 = 1.0f - wy1;
        const unsigned xb = __float_as_uint(fx);
        const unsigned yb = __float_as_uint(fy);
        const int off = (int)(yb * (unsigned)kBW + xb + kOffC);
        const float4 A = B4[off];        // (b0[y0,x0], b1[y0,x0], b0[y1,x0], b1[y1,x0])
        const float4 B = B4[off + 1];    // (b0[y0,x1], b1[y0,x1], b0[y1,x1], b1[y1,x1])
        const float h0 = fmaf(wx1, B.x, wx0 * A.x);
        const float h1 = fmaf(wx1, B.z, wx0 * A.z);
        acc0 = fmaf(wy0, h0, acc0);
        acc0 = fmaf(wy1, h1, acc0);
        const float g0 = fmaf(wx1, B.y, wx0 * A.y);
        const float g1 = fmaf(wx1, B.w, wx0 * A.w);
        acc1 = fmaf(wy0, g0, acc1);
        acc1 = fmaf(wy1, g1, acc1);
    }

    // ---- reduction over the 8 i-phases via smem ----
    __shared__ float red[2][16][9];   // pad to 9: conflict-free
    red[0][jl][io] = acc0;
    red[1][jl][io] = acc1;
    __syncthreads();

    if (t < 32) {
        const int b  = t >> 4;
        const int jj = t & 15;
        float sum = 0.0f;
        #pragma unroll
        for (int k = 0; k < 8; ++k) sum += red[b][jj][k];
        const int jo = jbase + jj;
        if (jo < kS) out[(b * kS + jo) * kT + th] = sum;
    }
}

extern "C" void kernel_launch(void* const* d_in, const int* in_sizes, int n_in,
                              void* d_out, int out_size)
{
    const float* img = (const float*)d_in[0];
    float* out = (float*)d_out;
    repack<<<(kBH * kBW + 255) / 256, 256>>>(img);
    dim3 grid((kS + 15) / 16, kT);
    radon_fwd<<<grid, 128>>>(out);
}

// round 13
// speedup vs baseline: 4.0120x; 1.5290x over previous
#include <cuda_runtime.h>
#include <cuda_fp16.h>

// Radon forward projection:
//   image (2,1,256,256) f32 -> sinogram (2,1,363,180) f32
// S=363; padded image occupies padded coords [53,309).
// px(i,j) = c*(j-181) + s*(i-181) + 181 ; py(i,j) = -s*(j-181) + c*(i-181) + 181
// out[b,0,j,t] = sum_i bilinear(padded_img_b, py, px)
//
// R8 design (fixed build): repack builds an fp16 quad-packed cell buffer with
// zero border:
//   cell(y,x) = fp16 x8 = (b0[y,x], b0[y,x+1] | b0[y+1,x], b0[y+1,x+1] |
//                          b1[y,x], b1[y,x+1] | b1[y+1,x], b1[y+1,x+1])
// over padded coords [50,313). One bilinear sample (both batches, all 8 taps)
// = ONE LDG.128. Interpolation weights + accumulation stay fp32; only tap
// storage is fp16 (norm rel err ~2e-4 << 1e-3). R3/R6 warp-patch skeleton.

namespace {
constexpr int   kS     = 363;
constexpr int   kT     = 180;
constexpr float kMagic = 8388608.0f;   // 2^23
constexpr int   kBW    = 264;          // buffer pitch (cells)
constexpr int   kBH    = 263;          // buffer rows
// off = (y0-50)*kBW + (x0-50), x0/y0 carried in low bits of magic floats:
constexpr unsigned kOffC = (unsigned)(0u - (0x4B000000u * (unsigned)kBW + 0x4B000000u) - 13250u);
}

__device__ uint4 g_hbuf[kBH * kBW];

__global__ void repack(const float* __restrict__ img)
{
    const int idx = blockIdx.x * blockDim.x + threadIdx.x;
    if (idx >= kBH * kBW) return;
    const int y = idx / kBW;
    const int x = idx - y * kBW;
    const int gx = x - 3;             // image coords of tap (x0)
    const int gy = y - 3;

    float t[8];
    #pragma unroll
    for (int b = 0; b < 2; ++b) {
        #pragma unroll
        for (int dy = 0; dy < 2; ++dy) {
            #pragma unroll
            for (int dx = 0; dx < 2; ++dx) {
                const int xx = gx + dx, yy = gy + dy;
                float v = 0.0f;
                if ((unsigned)xx < 256u && (unsigned)yy < 256u)
                    v = img[b * 65536 + yy * 256 + xx];
                t[b * 4 + dy * 2 + dx] = v;
            }
        }
    }
    __half2 p0 = __floats2half2_rn(t[0], t[1]);   // b0 row y0: x0,x1
    __half2 p1 = __floats2half2_rn(t[2], t[3]);   // b0 row y1
    __half2 p2 = __floats2half2_rn(t[4], t[5]);   // b1 row y0
    __half2 p3 = __floats2half2_rn(t[6], t[7]);   // b1 row y1
    uint4 cell;
    cell.x = *reinterpret_cast<unsigned*>(&p0);
    cell.y = *reinterpret_cast<unsigned*>(&p1);
    cell.z = *reinterpret_cast<unsigned*>(&p2);
    cell.w = *reinterpret_cast<unsigned*>(&p3);
    g_hbuf[idx] = cell;
}

__global__ void __launch_bounds__(128) radon_fwd(float* __restrict__ out)
{
    const int t     = threadIdx.x;
    const int th    = blockIdx.y;             // angle index
    const int jbase = blockIdx.x * 16;

    const float theta = (float)th * (180.0f / 179.0f) * 0.017453292519943295f;
    float s, c;
    sincosf(theta, &s, &c);
    const float as = fabsf(s), ac = fabsf(c);

    // pick warp patch shape minimizing image-row span J*|s| + I*|c|
    const float span0 = 16.f * as + 2.f * ac;   // (J,I)=(16,2)
    const float span1 =  8.f * as + 4.f * ac;   // (8,4)
    const float span2 =  4.f * as + 8.f * ac;   // (4,8)
    int jl, io;
    if (span0 <= span1 && span0 <= span2) {
        jl = t & 15;  io = t >> 4;
    } else if (span1 <= span2) {
        const int w = t >> 5;
        jl = (t & 7) | ((w & 1) << 3);
        io = ((t >> 3) & 3) | ((w >> 1) << 2);
    } else {
        const int w = t >> 5;
        io = t & 7;
        jl = ((t >> 3) & 3) | (w << 2);
    }

    const int j = jbase + jl;

    const float fj = (float)j - 181.0f;
    const float px_base = fmaf(c, fj, fmaf(-181.0f, s, 181.0f));
    const float py_base = fmaf(-s, fj, fmaf(-181.0f, c, 181.0f));

    // ---- outer clip: i-range where any tap can be nonzero (px,py in (52,309)) ----
    float lo = 0.0f, hi = 362.0f;
    bool empty = (j >= kS);
    {
        float d = s, b = px_base;
        #pragma unroll
        for (int axis = 0; axis < 2; ++axis) {
            if (fabsf(d) < 1e-7f) {
                if (b <= 52.0f || b >= 309.0f) empty = true;
            } else {
                float t0 = (52.0f  - b) / d;
                float t1 = (309.0f - b) / d;
                lo = fmaxf(lo, fminf(t0, t1));
                hi = fminf(hi, fmaxf(t0, t1));
            }
            d = c; b = py_base;
        }
    }
    lo = fmaxf(lo, 0.0f);
    hi = fminf(hi, 362.0f);

    int i_lo = 0, i_hi = -1;
    if (!empty && lo <= hi + 1.0f) {
        i_lo = max(0,   (int)floorf(lo) - 1);   // px,py stay within [50,311] here
        i_hi = min(362, (int)ceilf(hi) + 1);
    }

    float acc0 = 0.0f, acc1 = 0.0f;
    const uint4* __restrict__ H4 = g_hbuf;

    // strided loop: this thread owns i-phase `io`, stride 8; uniform gather
    const int i0 = i_lo + ((io - i_lo) & 7);
    #pragma unroll 4
    for (int i = i0; i <= i_hi; i += 8) {
        const float fi = (float)i;
        const float px = fmaf(s, fi, px_base);
        const float py = fmaf(c, fi, py_base);
        const float fx = __fadd_rz(px, kMagic);   // floor (px >= 50 > 0)
        const float fy = __fadd_rz(py, kMagic);
        const float xf = fx - kMagic, yf = fy - kMagic;
        const float wx1 = px - xf,    wy1 = py - yf;
        const float wx0 = 1.0f - wx1, wy0 = 1.0f - wy1;
        const unsigned xb = __float_as_uint(fx);
        const unsigned yb = __float_as_uint(fy);
        const int off = (int)(yb * (unsigned)kBW + xb + kOffC);
        const uint4 cell = H4[off];
        const float2 r0 = __half22float2(*reinterpret_cast<const __half2*>(&cell.x)); // b0 y0: x0,x1
        const float2 r1 = __half22float2(*reinterpret_cast<const __half2*>(&cell.y)); // b0 y1
        const float2 q0 = __half22float2(*reinterpret_cast<const __half2*>(&cell.z)); // b1 y0
        const float2 q1 = __half22float2(*reinterpret_cast<const __half2*>(&cell.w)); // b1 y1
        const float h0 = fmaf(wx1, r0.y, wx0 * r0.x);
        const float h1 = fmaf(wx1, r1.y, wx0 * r1.x);
        acc0 = fmaf(wy0, h0, acc0);
        acc0 = fmaf(wy1, h1, acc0);
        const float g0 = fmaf(wx1, q0.y, wx0 * q0.x);
        const float g1 = fmaf(wx1, q1.y, wx0 * q1.x);
        acc1 = fmaf(wy0, g0, acc1);
        acc1 = fmaf(wy1, g1, acc1);
    }

    // ---- reduction over the 8 i-phases via smem ----
    __shared__ float red[2][16][9];   // pad to 9: conflict-free
    red[0][jl][io] = acc0;
    red[1][jl][io] = acc1;
    __syncthreads();

    if (t < 32) {
        const int b  = t >> 4;
        const int jj = t & 15;
        float sum = 0.0f;
        #pragma unroll
        for (int k = 0; k < 8; ++k) sum += red[b][jj][k];
        const int jo = jbase + jj;
        if (jo < kS) out[(b * kS + jo) * kT + th] = sum;
    }
}

extern "C" void kernel_launch(void* const* d_in, const int* in_sizes, int n_in,
                              void* d_out, int out_size)
{
    const float* img = (const float*)d_in[0];
    float* out = (float*)d_out;
    repack<<<(kBH * kBW + 255) / 256, 256>>>(img);
    dim3 grid((kS + 15) / 16, kT);
    radon_fwd<<<grid, 128>>>(out);
}

// round 17
// speedup vs baseline: 4.0791x; 1.0167x over previous
#include <cuda_runtime.h>
#include <cuda_fp16.h>

// Radon forward projection:
//   image (2,1,256,256) f32 -> sinogram (2,1,363,180) f32
// S=363; padded image occupies padded coords [53,309).
// px(i,j) = c*(j-181) + s*(i-181) + 181 ; py(i,j) = -s*(j-181) + c*(i-181) + 181
// out[b,0,j,t] = sum_i bilinear(padded_img_b, py, px)
//
// R13: fp16 quad-packed cells (one LDG.128 = all 8 taps, both batches) with
// zero border [50,313). y-interpolation now runs in packed half2 (HMUL2/HFMA2,
// broadcast fp16 y-weights); x-interp + accumulation stay fp32. Float sample
// counter (exact for ints <= 363) replaces per-iter I2F. R3/R6 warp-patch
// skeleton + i-phase smem reduction.

namespace {
constexpr int   kS     = 363;
constexpr int   kT     = 180;
constexpr float kMagic = 8388608.0f;   // 2^23
constexpr int   kBW    = 264;          // buffer pitch (cells)
constexpr int   kBH    = 263;          // buffer rows
// off = (y0-50)*kBW + (x0-50), x0/y0 carried in low bits of magic floats:
constexpr unsigned kOffC = (unsigned)(0u - (0x4B000000u * (unsigned)kBW + 0x4B000000u) - 13250u);
}

__device__ uint4 g_hbuf[kBH * kBW];

__global__ void repack(const float* __restrict__ img)
{
    const int idx = blockIdx.x * blockDim.x + threadIdx.x;
    if (idx >= kBH * kBW) return;
    const int y = idx / kBW;
    const int x = idx - y * kBW;
    const int gx = x - 3;             // image coords of tap (x0)
    const int gy = y - 3;

    float t[8];
    #pragma unroll
    for (int b = 0; b < 2; ++b) {
        #pragma unroll
        for (int dy = 0; dy < 2; ++dy) {
            #pragma unroll
            for (int dx = 0; dx < 2; ++dx) {
                const int xx = gx + dx, yy = gy + dy;
                float v = 0.0f;
                if ((unsigned)xx < 256u && (unsigned)yy < 256u)
                    v = img[b * 65536 + yy * 256 + xx];
                t[b * 4 + dy * 2 + dx] = v;
            }
        }
    }
    __half2 p0 = __floats2half2_rn(t[0], t[1]);   // b0 row y0: x0,x1
    __half2 p1 = __floats2half2_rn(t[2], t[3]);   // b0 row y1
    __half2 p2 = __floats2half2_rn(t[4], t[5]);   // b1 row y0
    __half2 p3 = __floats2half2_rn(t[6], t[7]);   // b1 row y1
    uint4 cell;
    cell.x = *reinterpret_cast<unsigned*>(&p0);
    cell.y = *reinterpret_cast<unsigned*>(&p1);
    cell.z = *reinterpret_cast<unsigned*>(&p2);
    cell.w = *reinterpret_cast<unsigned*>(&p3);
    g_hbuf[idx] = cell;
}

__global__ void __launch_bounds__(128) radon_fwd(float* __restrict__ out)
{
    const int t     = threadIdx.x;
    const int th    = blockIdx.y;             // angle index
    const int jbase = blockIdx.x * 16;

    const float theta = (float)th * (180.0f / 179.0f) * 0.017453292519943295f;
    float s, c;
    sincosf(theta, &s, &c);
    const float as = fabsf(s), ac = fabsf(c);

    // pick warp patch shape minimizing image-row span J*|s| + I*|c|
    const float span0 = 16.f * as + 2.f * ac;   // (J,I)=(16,2)
    const float span1 =  8.f * as + 4.f * ac;   // (8,4)
    const float span2 =  4.f * as + 8.f * ac;   // (4,8)
    int jl, io;
    if (span0 <= span1 && span0 <= span2) {
        jl = t & 15;  io = t >> 4;
    } else if (span1 <= span2) {
        const int w = t >> 5;
        jl = (t & 7) | ((w & 1) << 3);
        io = ((t >> 3) & 3) | ((w >> 1) << 2);
    } else {
        const int w = t >> 5;
        io = t & 7;
        jl = ((t >> 3) & 3) | (w << 2);
    }

    const int j = jbase + jl;

    const float fj = (float)j - 181.0f;
    const float px_base = fmaf(c, fj, fmaf(-181.0f, s, 181.0f));
    const float py_base = fmaf(-s, fj, fmaf(-181.0f, c, 181.0f));

    // ---- outer clip: i-range where any tap can be nonzero (px,py in (52,309)) ----
    float lo = 0.0f, hi = 362.0f;
    bool empty = (j >= kS);
    {
        float d = s, b = px_base;
        #pragma unroll
        for (int axis = 0; axis < 2; ++axis) {
            if (fabsf(d) < 1e-7f) {
                if (b <= 52.0f || b >= 309.0f) empty = true;
            } else {
                float t0 = (52.0f  - b) / d;
                float t1 = (309.0f - b) / d;
                lo = fmaxf(lo, fminf(t0, t1));
                hi = fminf(hi, fmaxf(t0, t1));
            }
            d = c; b = py_base;
        }
    }
    lo = fmaxf(lo, 0.0f);
    hi = fminf(hi, 362.0f);

    int i_lo = 0, i_hi = -1;
    if (!empty && lo <= hi + 1.0f) {
        i_lo = max(0,   (int)floorf(lo) - 1);   // px,py stay within [50,311] here
        i_hi = min(362, (int)ceilf(hi) + 1);
    }

    float acc0 = 0.0f, acc1 = 0.0f;
    const uint4* __restrict__ H4 = g_hbuf;

    // strided loop: this thread owns i-phase `io`, stride 8; uniform gather.
    // fi tracks i exactly in fp32 (integers <= 363 are exact).
    const int i0 = i_lo + ((io - i_lo) & 7);
    float fi = (float)i0;
    #pragma unroll 4
    for (int i = i0; i <= i_hi; i += 8, fi += 8.0f) {
        const float px = fmaf(s, fi, px_base);
        const float py = fmaf(c, fi, py_base);
        const float fx = __fadd_rz(px, kMagic);   // floor (px >= 50 > 0)
        const float fy = __fadd_rz(py, kMagic);
        const float xf = fx - kMagic, yf = fy - kMagic;
        const float wx1 = px - xf,    wy1 = py - yf;
        const float wx0 = 1.0f - wx1, wy0 = 1.0f - wy1;
        const unsigned xb = __float_as_uint(fx);
        const unsigned yb = __float_as_uint(fy);
        const int off = (int)(yb * (unsigned)kBW + xb + kOffC);
        const uint4 cell = H4[off];
        // y-interp in packed half2 (both x taps at once, per batch)
        const __half2 wy0h = __float2half2_rn(wy0);
        const __half2 wy1h = __float2half2_rn(wy1);
        __half2 v0 = __hmul2(*reinterpret_cast<const __half2*>(&cell.x), wy0h);
        v0 = __hfma2(*reinterpret_cast<const __half2*>(&cell.y), wy1h, v0);   // b0: (x0,x1)
        __half2 v1 = __hmul2(*reinterpret_cast<const __half2*>(&cell.z), wy0h);
        v1 = __hfma2(*reinterpret_cast<const __half2*>(&cell.w), wy1h, v1);   // b1: (x0,x1)
        const float2 f0 = __half22float2(v0);
        const float2 f1 = __half22float2(v1);
        // x-interp + accumulate in fp32
        acc0 = fmaf(wx0, f0.x, acc0);
        acc0 = fmaf(wx1, f0.y, acc0);
        acc1 = fmaf(wx0, f1.x, acc1);
        acc1 = fmaf(wx1, f1.y, acc1);
    }

    // ---- reduction over the 8 i-phases via smem ----
    __shared__ float red[2][16][9];   // pad to 9: conflict-free
    red[0][jl][io] = acc0;
    red[1][jl][io] = acc1;
    __syncthreads();

    if (t < 32) {
        const int b  = t >> 4;
        const int jj = t & 15;
        float sum = 0.0f;
        #pragma unroll
        for (int k = 0; k < 8; ++k) sum += red[b][jj][k];
        const int jo = jbase + jj;
        if (jo < kS) out[(b * kS + jo) * kT + th] = sum;
    }
}

extern "C" void kernel_launch(void* const* d_in, const int* in_sizes, int n_in,
                              void* d_out, int out_size)
{
    const float* img = (const float*)d_in[0];
    float* out = (float*)d_out;
    repack<<<(kBH * kBW + 255) / 256, 256>>>(img);
    dim3 grid((kS + 15) / 16, kT);
    radon_fwd<<<grid, 128>>>(out);
}